// round 16
// baseline (speedup 1.0000x reference)
#include <cuda_runtime.h>
#include <cuda_fp16.h>
#include <cstdint>

#define BB   2
#define AA   512
#define TT   512
#define NF   128
#define NRBF 25
#define TILT 64           // block t-tile: 2 quads x 32 rows
#define NTIL (TT / TILT)  // 8

// quad region: [W: 32*136*2 = 8704][A2: 16*512 = 8192, rbf in first 2560]
#define QW_B  8704
#define QRB   16896

__device__ __half2  g_y2[BB * AA * NF / 2];
__device__ uint32_t g_w1ph[2 * 32 * 32];   // fp16 Wf1 B-frags (bf1 @ k=25)
__device__ uint32_t g_w2ph[8 * 32 * 32];   // fp16 Wf2 B-frags

__device__ __forceinline__ float ssp(float v) {
    const float m = fmaxf(v, 0.0f);
    const float u = __expf(-fabsf(v));
    const float x = fmaf(2.0f, u, -1.0f);
    float p = -0.00342936f;
    p = fmaf(p, x, 0.01337449f);
    p = fmaf(p, x, -0.05542695f);
    p = fmaf(p, x, 0.33307613f);
    p = fmaf(p, x, -0.28768922f);   // 0.40545796 - ln2
    return m + p;
}
__device__ __forceinline__ uint32_t smem_u32(const void* p) {
    uint32_t a;
    asm("{ .reg .u64 t; cvta.to.shared.u64 t, %1; cvt.u32.u64 %0, t; }"
        : "=r"(a) : "l"(p));
    return a;
}
__device__ __forceinline__ void mma16(float* c, const uint32_t* a,
                                      uint32_t b0, uint32_t b1) {
    asm volatile(
        "mma.sync.aligned.m16n8k16.row.col.f32.f16.f16.f32 "
        "{%0,%1,%2,%3}, {%4,%5,%6,%7}, {%8,%9}, {%0,%1,%2,%3};"
        : "+f"(c[0]), "+f"(c[1]), "+f"(c[2]), "+f"(c[3])
        : "r"(a[0]), "r"(a[1]), "r"(a[2]), "r"(a[3]), "r"(b0), "r"(b1));
}
__device__ __forceinline__ void ldmat4(uint32_t* r, uint32_t addr) {
    asm volatile(
        "ldmatrix.sync.aligned.m8n8.x4.shared.b16 {%0,%1,%2,%3}, [%4];"
        : "=r"(r[0]), "=r"(r[1]), "=r"(r[2]), "=r"(r[3]) : "r"(addr));
}
__device__ __forceinline__ uint32_t packh2(float lo, float hi) {
    __half2 h = __floats2half2_rn(lo, hi);
    return *reinterpret_cast<uint32_t*>(&h);
}
#define QBAR(id) asm volatile("bar.sync %0, 128;" :: "r"(id) : "memory")

// ---------------------------------------------------------------------------
// fused prep + in2f (y fp16); bf1 folded into k=25 of w1 table
// ---------------------------------------------------------------------------
__global__ void prep_in2f_kernel(const float* __restrict__ x,
                                 const float* __restrict__ Win,
                                 const float* __restrict__ Wf1,
                                 const float* __restrict__ Wf2,
                                 const float* __restrict__ bf1) {
    if (blockIdx.x < 256) {
        __shared__ float xs[4][NF];
        const int row4 = blockIdx.x * 4;
        for (int i = threadIdx.x; i < 4 * NF; i += 256)
            xs[i >> 7][i & 127] = x[(row4 + (i >> 7)) * NF + (i & 127)];
        __syncthreads();
        const int sub = threadIdx.x >> 6;
        const int f0 = (threadIdx.x & 63) * 2;
        float a0 = 0.0f, a1 = 0.0f;
#pragma unroll 8
        for (int i = 0; i < NF; ++i) {
            a0 += xs[sub][i] * Win[i * NF + f0];
            a1 += xs[sub][i] * Win[i * NF + f0 + 1];
        }
        g_y2[((row4 + sub) * NF + f0) >> 1] = __floats2half2_rn(a0, a1);
    } else {
        const int idx = (blockIdx.x - 256) * 256 + threadIdx.x;
        if (idx < 2048) {
            const int ks = idx >> 10, rem = idx & 1023;
            const int lane = rem >> 5, i = rem & 31;
            const int j = i >> 1, r = i & 1;
            const int n = j * 8 + (lane >> 2);
            const int k0 = ks * 16 + r * 8 + (lane & 3) * 2;
            const float v0 = (k0 < NRBF) ? Wf1[k0 * NF + n]
                           : (k0 == NRBF ? bf1[n] : 0.0f);
            const float v1 = (k0 + 1 < NRBF) ? Wf1[(k0 + 1) * NF + n]
                           : (k0 + 1 == NRBF ? bf1[n] : 0.0f);
            const int off = (ks * 32 + lane) * 32 +
                            ((((i >> 2) ^ (lane & 7)) << 2) + (i & 3));
            g_w1ph[off] = packh2(v0, v1);
        } else if (idx < 2048 + 8192) {
            const int t = idx - 2048;
            const int ks = t >> 10, rem = t & 1023;
            const int lane = rem >> 5, i = rem & 31;
            const int j = i >> 1, r = i & 1;
            const int n = j * 8 + (lane >> 2);
            const int k0 = ks * 16 + r * 8 + (lane & 3) * 2;
            const int off = (ks * 32 + lane) * 32 +
                            ((((i >> 2) ^ (lane & 7)) << 2) + (i & 3));
            g_w2ph[off] = packh2(Wf2[k0 * NF + n], Wf2[(k0 + 1) * NF + n]);
        }
    }
}

// ---------------------------------------------------------------------------
// SMEM layout (bytes)
// ---------------------------------------------------------------------------
#define OFF_W2P   0          // 32768
#define OFF_QB    32768      // 2 * 16896 = 33792
#define OFF_BF2   66560      // 512
#define OFF_MASK  67072      // 2*64*4 = 512 (double-buffered)
#define OFF_NJ    67584      // 512
#define OFF_NK    68096      // 512
#define SMEM_BYTES 68608     // 67KB -> 3 blocks/SM

#define NTHREADS 256

__global__ __launch_bounds__(NTHREADS, 3)
void cfconv_mma(const float* __restrict__ r_ij,
                const float* __restrict__ pmask,
                const float* __restrict__ bf2,
                const float* __restrict__ Wout, const float* __restrict__ bout,
                const int* __restrict__ nj, const int* __restrict__ nk,
                float* __restrict__ out) {
    extern __shared__ __align__(16) char smem[];
    uint32_t* sW2p  = (uint32_t*)(smem + OFF_W2P);
    float* sBf2  = (float*)(smem + OFF_BF2);
    float* sMask = (float*)(smem + OFF_MASK);   // [2][64]
    int*   sNj   = (int*)(smem + OFF_NJ);
    int*   sNk   = (int*)(smem + OFF_NK);
    float* sPart = (float*)(smem + OFF_QB);     // post-loop aliases
    float* sY    = (float*)(smem + OFF_QB + 4096);
    float* sRed  = (float*)(smem + OFF_QB + 4608);

    const int tid  = threadIdx.x;
    const int wid  = tid >> 5;
    const int lane = tid & 31;
    const int gid  = lane >> 2;
    const int l4   = lane & 3;
    const int quad = wid >> 2;        // 0..1
    const int qw   = wid & 3;         // warp within quad: GEMM1 gc-pair, GEMM2 f-quarter
    const int f4   = lane * 4;
    const int a = blockIdx.x, b = blockIdx.y;
    const int ba = b * AA + a;
    const __half* Yb = (const __half*)g_y2 + (long)b * AA * NF;

    char* qb = smem + OFF_QB + quad * QRB;
    __half* pW  = (__half*)qb;                 // W rows: 32 x 136 halves
    char*   pA2 = qb + QW_B;                   // A2 frags (rbf in first 2560B)
    __half* pRbf = (__half*)pA2;
    const uint32_t a2u  = smem_u32(pA2);
    const int barid = quad + 1;
    const int qrow = quad * 32;                // quad's row base in 64-row tile

    // staging map: 4 lanes per row, 8 cols each (one STS.128)
    const int ltid = tid & 127;
    const int srow = ltid >> 2;                // 0..31
    const int scol = (ltid & 3) * 8;

    // ldmatrix map for rbf A-frags
    const int lrow = (lane & 7) + ((lane >> 3) & 1) * 8;
    const int lkh  = ((lane >> 4) & 1) * 8;
    const uint32_t addrR = a2u + (uint32_t)((lrow * 40 + lkh) * 2);

    // ---- prologue ----
    {
        const uint4* src2 = (const uint4*)g_w2ph;
        uint4* dst2 = (uint4*)sW2p;
        for (int i = tid; i < 2048; i += NTHREADS) dst2[i] = src2[i];
    }
    if (tid < NF) sBf2[tid] = bf2[tid];

    // tile-invariant W1 B-fragments for this warp's two gc (from L2)
    uint4 w1a, w1b2, w1c, w1d;
    {
        const int gc0 = qw * 2, gc1 = qw * 2 + 1;
        const uint4* r0 = (const uint4*)g_w1ph + lane * 8;         // ks=0
        const uint4* r1 = (const uint4*)g_w1ph + (32 + lane) * 8;  // ks=1
        w1a  = __ldg(r0 + (gc0 ^ (lane & 7)));
        w1b2 = __ldg(r1 + (gc0 ^ (lane & 7)));
        w1c  = __ldg(r0 + (gc1 ^ (lane & 7)));
        w1d  = __ldg(r1 + (gc1 ^ (lane & 7)));
    }
    __syncthreads();

    float4 acc0 = make_float4(0.f, 0.f, 0.f, 0.f);
    float4 acc1 = make_float4(0.f, 0.f, 0.f, 0.f);

    for (int tile = 0; tile < NTIL; ++tile) {
        const int mb = (tile & 1) * 64 + qrow;   // meta buffer base for quad

        // ---- stage rbf (32 rows, K padded: col25=1, 26..31=0) + meta ----
        {
            const long tg = (long)ba * TT + tile * TILT;
            const float* rs = r_ij + (tg + qrow + srow) * NRBF;
            uint32_t h2[4];
#pragma unroll
            for (int q = 0; q < 4; ++q) {
                const int c0 = scol + q * 2, c1 = c0 + 1;
                const float v0 = (c0 < NRBF) ? rs[c0] : (c0 == NRBF ? 1.0f : 0.0f);
                const float v1 = (c1 < NRBF) ? rs[c1] : (c1 == NRBF ? 1.0f : 0.0f);
                h2[q] = packh2(v0, v1);
            }
            *(uint4*)((char*)pRbf + (srow * 40 + scol) * 2) =
                make_uint4(h2[0], h2[1], h2[2], h2[3]);
            if (ltid < 32) {
                const long p = tg + qrow + ltid;
                sMask[mb + ltid] = pmask[p];
                sNj[mb + ltid] = nj[p];
                sNk[mb + ltid] = nk[p];
            }
        }
        QBAR(barid);                 // A: stage complete

        // ---- rbf A-frags: 2 Msets x 2 k-halves ----
        uint32_t Ar[4][4];
        ldmat4(Ar[0], addrR);                 // Mset0 k0-15
        ldmat4(Ar[1], addrR + 32);            // Mset0 k16-31
        ldmat4(Ar[2], addrR + 1280);          // Mset1 k0-15
        ldmat4(Ar[3], addrR + 1280 + 32);     // Mset1 k16-31
        QBAR(barid);                 // B: rbf consumed; A2 stores may clobber

        // ---- GEMM1 + ssp for own 2 gc over 32 rows -> A2 exchange ----
#pragma unroll
        for (int g2 = 0; g2 < 2; ++g2) {
            const int gc = qw * 2 + g2;
            const uint4 q0 = g2 ? w1c : w1a;   // ks=0 (k 0-15)
            const uint4 q1 = g2 ? w1d : w1b2;  // ks=1 (k 16-31)
#pragma unroll
            for (int m = 0; m < 2; ++m) {
                float C1[8] = {0.f, 0.f, 0.f, 0.f, 0.f, 0.f, 0.f, 0.f};
                mma16(C1,     Ar[m * 2],     q0.x, q0.y);
                mma16(C1 + 4, Ar[m * 2],     q0.z, q0.w);
                mma16(C1,     Ar[m * 2 + 1], q1.x, q1.y);
                mma16(C1 + 4, Ar[m * 2 + 1], q1.z, q1.w);
                const uint32_t a0 = packh2(ssp(C1[0]), ssp(C1[1]));
                const uint32_t a1 = packh2(ssp(C1[2]), ssp(C1[3]));
                const uint32_t a2 = packh2(ssp(C1[4]), ssp(C1[5]));
                const uint32_t a3 = packh2(ssp(C1[6]), ssp(C1[7]));
                asm volatile("st.shared.v4.b32 [%0], {%1,%2,%3,%4};"
                    :: "r"(a2u + (uint32_t)(((gc * 2 + m) << 9) + lane * 16)),
                       "r"(a0), "r"(a1), "r"(a2), "r"(a3) : "memory");
            }
        }
        QBAR(barid);                 // C: all A2 frags ready

        // ---- GEMM2: all 8 gc, M=32, own f-quarter (N=32) ----
        float C2[2][4][4];
#pragma unroll
        for (int m = 0; m < 2; ++m)
#pragma unroll
            for (int j = 0; j < 4; ++j)
#pragma unroll
                for (int q = 0; q < 4; ++q) C2[m][j][q] = 0.0f;
#pragma unroll
        for (int gc = 0; gc < 8; ++gc) {
            uint32_t A2r[2][4];
#pragma unroll
            for (int m = 0; m < 2; ++m)
                asm volatile("ld.shared.v4.b32 {%0,%1,%2,%3}, [%4];"
                    : "=r"(A2r[m][0]), "=r"(A2r[m][1]),
                      "=r"(A2r[m][2]), "=r"(A2r[m][3])
                    : "r"(a2u + (uint32_t)(((gc * 2 + m) << 9) + lane * 16)));
            const uint4* r2 = (const uint4*)sW2p + (gc * 32 + lane) * 8;
            const uint4 qa = r2[(qw * 2) ^ (lane & 7)];
            const uint4 qb2 = r2[(qw * 2 + 1) ^ (lane & 7)];
#pragma unroll
            for (int m = 0; m < 2; ++m) {
                mma16(C2[m][0], A2r[m], qa.x, qa.y);
                mma16(C2[m][1], A2r[m], qa.z, qa.w);
                mma16(C2[m][2], A2r[m], qb2.x, qb2.y);
                mma16(C2[m][3], A2r[m], qb2.z, qb2.w);
            }
        }

        // ---- store (C2 + bf2) * mask as fp16 -> W rows (own f-quarter) ----
        {
            const float mk[4] = {sMask[mb + gid],      sMask[mb + gid + 8],
                                 sMask[mb + gid + 16], sMask[mb + gid + 24]};
#pragma unroll
            for (int j = 0; j < 4; ++j) {
                const int f0 = qw * 32 + j * 8 + l4 * 2;
                const float2 b2 = *(const float2*)(sBf2 + f0);
#pragma unroll
                for (int m = 0; m < 2; ++m) {
                    *(__half2*)(pW + (gid + m * 16) * 136 + f0) =
                        __floats2half2_rn((C2[m][j][0] + b2.x) * mk[m * 2],
                                          (C2[m][j][1] + b2.y) * mk[m * 2]);
                    *(__half2*)(pW + (gid + 8 + m * 16) * 136 + f0) =
                        __floats2half2_rn((C2[m][j][2] + b2.x) * mk[m * 2 + 1],
                                          (C2[m][j][3] + b2.y) * mk[m * 2 + 1]);
                }
            }
        }
        QBAR(barid);                 // D: W complete (all quarters)

        // ---- row-coalesced gather epilogue over own 8 rows ----
#pragma unroll
        for (int rr = 0; rr < 8; rr += 2) {
#pragma unroll
            for (int hh = 0; hh < 2; ++hh) {
                const int rl = qw * 8 + rr + hh;
                const uint2 yju = *(const uint2*)(Yb + sNj[mb + rl] * NF + f4);
                const uint2 yku = *(const uint2*)(Yb + sNk[mb + rl] * NF + f4);
                const uint2 wu  = *(const uint2*)(pW + rl * 136 + f4);
                const float2 ja = __half22float2(*(const __half2*)&yju.x);
                const float2 jb = __half22float2(*(const __half2*)&yju.y);
                const float2 ka = __half22float2(*(const __half2*)&yku.x);
                const float2 kb = __half22float2(*(const __half2*)&yku.y);
                const float2 wlo = __half22float2(*(const __half2*)&wu.x);
                const float2 whi = __half22float2(*(const __half2*)&wu.y);
                float4& av = hh ? acc1 : acc0;
                av.x = fmaf(wlo.x, ja.x * ka.x, av.x);
                av.y = fmaf(wlo.y, ja.y * ka.y, av.y);
                av.z = fmaf(whi.x, jb.x * kb.x, av.z);
                av.w = fmaf(whi.y, jb.y * kb.y, av.w);
            }
        }
        // next-tile staging writes rbf (inside A2 region) + other meta buffer:
        // partner GEMM2 ended before QBAR-D; epilogue touches only W + gmem. Safe.
    }

    __syncthreads();
    // ---- cross-warp reduce (each warp covered disjoint rows, full f) ----
    {
        float4 accv = make_float4(acc0.x + acc1.x, acc0.y + acc1.y,
                                  acc0.z + acc1.z, acc0.w + acc1.w);
        *(float4*)(sPart + wid * NF + f4) = accv;
    }
    __syncthreads();
    if (tid < NF) {
        float s = 0.0f;
#pragma unroll
        for (int w = 0; w < 8; ++w) s += sPart[w * NF + tid];
        sY[tid] = s;
    }
    __syncthreads();

    // ---- f2out: out = ssp(y @ Wout + bout) ----
    {
        const int o = tid & 127;
        const int q = tid >> 7;
        float s = 0.0f;
        const float* Wp = Wout + q * 64 * NF + o;
#pragma unroll 8
        for (int f = 0; f < 64; ++f) s += sY[q * 64 + f] * Wp[f * NF];
        sRed[q * NF + o] = s;
    }
    __syncthreads();
    if (tid < NF)
        out[(long)ba * NF + tid] = ssp(sRed[tid] + sRed[NF + tid] + bout[tid]);
}

// ---------------------------------------------------------------------------
extern "C" void kernel_launch(void* const* d_in, const int* in_sizes, int n_in,
                              void* d_out, int out_size) {
    const float* x    = (const float*)d_in[0];
    const float* r_ij = (const float*)d_in[1];
    const float* mask = (const float*)d_in[2];
    const float* Wf1  = (const float*)d_in[3];
    const float* bf1  = (const float*)d_in[4];
    const float* Wf2  = (const float*)d_in[5];
    const float* bf2  = (const float*)d_in[6];
    const float* Win  = (const float*)d_in[7];
    const float* Wout = (const float*)d_in[8];
    const float* bout = (const float*)d_in[9];
    const int*   nj   = (const int*)d_in[10];
    const int*   nk   = (const int*)d_in[11];
    float* out = (float*)d_out;

    prep_in2f_kernel<<<296, 256>>>(x, Win, Wf1, Wf2, bf1);

    cudaFuncSetAttribute(cfconv_mma,
                         cudaFuncAttributeMaxDynamicSharedMemorySize, SMEM_BYTES);
    dim3 grid(AA, BB);
    cfconv_mma<<<grid, NTHREADS, SMEM_BYTES>>>(r_ij, mask, bf2,
                                               Wout, bout, nj, nk, out);
}